// round 1
// baseline (speedup 1.0000x reference)
#include <cuda_runtime.h>

#define N_NODES 50000
#define D       128
#define N_EDGES 800000

// Scratch for transformed = feat @ weight (25.6 MB). Static __device__ array:
// no allocation, graph-capture safe.
__device__ float g_transformed[N_NODES * D];

typedef unsigned long long u64;

__device__ __forceinline__ u64 pack2(float x) {
    u64 r;
    asm("mov.b64 %0, {%1, %1};" : "=l"(r) : "f"(x));
    return r;
}
__device__ __forceinline__ void ffma2(u64 &d, u64 a, u64 b) {
    asm("fma.rn.f32x2 %0, %1, %2, %0;" : "+l"(d) : "l"(a), "l"(b));
}
__device__ __forceinline__ float2 unpack2(u64 v) {
    float2 f;
    asm("mov.b64 {%0, %1}, %2;" : "=f"(f.x), "=f"(f.y) : "l"(v));
    return f;
}

// ---------------------------------------------------------------------------
// Kernel A: one pass over feat computes BOTH
//   g_transformed = feat @ W
//   out           = feat @ LW + bias
// Block = 256 threads (8 warps), 32 rows per block, 4 rows per warp.
// Lane computes 4 columns (col = lane*4). W rows read as LDG.128 (L1-hot,
// 64 KB each); feat tile staged in smem; packed f32x2 FMA halves issue count.
// ---------------------------------------------------------------------------
__global__ __launch_bounds__(256) void gemm_dual_kernel(
    const float* __restrict__ feat,
    const float* __restrict__ W,
    const float* __restrict__ bias,
    const float* __restrict__ LW,
    float* __restrict__ out)
{
    __shared__ float sfeat[32][D];

    const int row0  = blockIdx.x * 32;
    int nrows = N_NODES - row0;
    if (nrows > 32) nrows = 32;

    // Stage feat rows into smem (float4 copies)
    {
        const float4* s4 = (const float4*)(feat + (size_t)row0 * D);
        float4*       d4 = (float4*)&sfeat[0][0];
        const int total = nrows * (D / 4);
        for (int i = threadIdx.x; i < total; i += 256) d4[i] = s4[i];
    }
    __syncthreads();

    const int warp = threadIdx.x >> 5;
    const int lane = threadIdx.x & 31;
    const int r0   = warp * 4;        // first row (within block) for this warp
    const int col  = lane * 4;        // 4 output columns for this lane

    u64 accw[4][2], accl[4][2];
#pragma unroll
    for (int r = 0; r < 4; r++) {
        accw[r][0] = 0ull; accw[r][1] = 0ull;
        accl[r][0] = 0ull; accl[r][1] = 0ull;
    }

#pragma unroll 8
    for (int k = 0; k < D; k++) {
        const ulonglong2 wa = *(const ulonglong2*)(W  + (size_t)k * D + col);
        const ulonglong2 wl = *(const ulonglong2*)(LW + (size_t)k * D + col);
#pragma unroll
        for (int r = 0; r < 4; r++) {
            const u64 a2 = pack2(sfeat[r0 + r][k]);   // smem broadcast
            ffma2(accw[r][0], a2, wa.x);
            ffma2(accw[r][1], a2, wa.y);
            ffma2(accl[r][0], a2, wl.x);
            ffma2(accl[r][1], a2, wl.y);
        }
    }

    const float4 b4 = *(const float4*)(bias + col);

#pragma unroll
    for (int r = 0; r < 4; r++) {
        const int lrow = r0 + r;
        if (lrow < nrows) {
            const size_t off = (size_t)(row0 + lrow) * D + col;
            const float2 w0 = unpack2(accw[r][0]);
            const float2 w1 = unpack2(accw[r][1]);
            float4 tv; tv.x = w0.x; tv.y = w0.y; tv.z = w1.x; tv.w = w1.y;
            *(float4*)(g_transformed + off) = tv;

            const float2 l0 = unpack2(accl[r][0]);
            const float2 l1 = unpack2(accl[r][1]);
            float4 ov;
            ov.x = l0.x + b4.x; ov.y = l0.y + b4.y;
            ov.z = l1.x + b4.z; ov.w = l1.y + b4.w;
            *(float4*)(out + off) = ov;
        }
    }
}

// ---------------------------------------------------------------------------
// Kernel B: edge scatter. One warp per edge: gather 512B row of g_transformed
// (L2-resident) and reduce into out[dst] with 16B vector reductions
// (red.global.add.v4.f32), 4 ops per lane-warp => 8 red ops per edge total.
// ---------------------------------------------------------------------------
__global__ __launch_bounds__(256) void scatter_kernel(
    const int* __restrict__ src,
    const int* __restrict__ dst,
    float* __restrict__ out)
{
    const int lane   = threadIdx.x & 31;
    const int gwarp  = (blockIdx.x * blockDim.x + threadIdx.x) >> 5;
    const int nwarps = (gridDim.x * blockDim.x) >> 5;

    for (int e = gwarp; e < N_EDGES; e += nwarps) {
        const int s = src[e];
        const int d = dst[e];
        const float4 v = *(const float4*)(g_transformed + (size_t)s * D + lane * 4);
        float* p = out + (size_t)d * D + lane * 4;
        asm volatile("red.global.add.v4.f32 [%0], {%1, %2, %3, %4};"
                     :: "l"(p), "f"(v.x), "f"(v.y), "f"(v.z), "f"(v.w)
                     : "memory");
    }
}

extern "C" void kernel_launch(void* const* d_in, const int* in_sizes, int n_in,
                              void* d_out, int out_size)
{
    const float* feat   = (const float*)d_in[0];
    const float* weight = (const float*)d_in[1];
    const float* h_bias = (const float*)d_in[2];
    const float* loop_w = (const float*)d_in[3];
    const int*   src    = (const int*)d_in[4];
    const int*   dst    = (const int*)d_in[5];
    float*       out    = (float*)d_out;

    gemm_dual_kernel<<<(N_NODES + 31) / 32, 256>>>(feat, weight, h_bias, loop_w, out);
    scatter_kernel<<<2048, 256>>>(src, dst, out);
}